// round 1
// baseline (speedup 1.0000x reference)
#include <cuda_runtime.h>

#define N_TOTAL 10000
#define D 128
#define BSZ 100
#define FEAT 3072
#define TOPK 50

// ---------------- scratch (device globals: no allocation allowed) ----------
__device__ float g_x[(size_t)N_TOTAL * D];                 // pre-BN linear out
__device__ float g_y[(size_t)N_TOTAL * D];                 // -2 * out * sw
__device__ float g_a[N_TOTAL];                             // sum_k sw*out^2
__device__ float g_scores[(size_t)N_TOTAL * N_TOTAL];      // 400 MB scratch

// ---------------- f32x2 helpers (packed FFMA2) -----------------------------
__device__ __forceinline__ unsigned long long pack2(float x, float y) {
    unsigned long long r;
    asm("mov.b64 %0, {%1, %2};" : "=l"(r) : "f"(x), "f"(y));
    return r;
}
__device__ __forceinline__ float2 unpack2(unsigned long long v) {
    float x, y;
    asm("mov.b64 {%0, %1}, %2;" : "=f"(x), "=f"(y) : "l"(v));
    return make_float2(x, y);
}
__device__ __forceinline__ void fma2(unsigned long long& c,
                                     unsigned long long a,
                                     unsigned long long b) {
    asm("fma.rn.f32x2 %0, %1, %2, %3;" : "=l"(c) : "l"(a), "l"(b), "l"(c));
}

// ===========================================================================
// Kernel 1: x = inputs @ W1^T + b1      (M=10000, N=128, K=3072)
// Tile: 64 (M) x 128 (N), K-chunks of 32, 256 threads, 4x8 micro-tile.
// ===========================================================================
__global__ void gemm1_kernel(const float* __restrict__ A,
                             const float* __restrict__ W,
                             const float* __restrict__ b1) {
    __shared__ __align__(16) float As[64][36];
    __shared__ float Bs[32][132];

    const int tid = threadIdx.x;
    const int mbase = blockIdx.x * 64;
    const int r0 = (tid >> 4) * 4;
    const int c0 = (tid & 15) * 8;

    unsigned long long acc[4][4];
#pragma unroll
    for (int i = 0; i < 4; ++i)
#pragma unroll
        for (int u = 0; u < 4; ++u) acc[i][u] = 0ULL;

    const int lr = tid >> 3;          // 0..31
    const int lk = (tid & 7) * 4;     // 0,4,...,28

    for (int kc = 0; kc < FEAT; kc += 32) {
#pragma unroll
        for (int it = 0; it < 2; ++it) {
            int m = mbase + it * 32 + lr;
            float4 v = make_float4(0.f, 0.f, 0.f, 0.f);
            if (m < N_TOTAL)
                v = *(const float4*)&A[(size_t)m * FEAT + kc + lk];
            *(float4*)&As[it * 32 + lr][lk] = v;
        }
#pragma unroll
        for (int it = 0; it < 4; ++it) {
            int n = it * 32 + lr;     // 0..127, always valid
            float4 v = *(const float4*)&W[(size_t)n * FEAT + kc + lk];
            Bs[lk + 0][n] = v.x;
            Bs[lk + 1][n] = v.y;
            Bs[lk + 2][n] = v.z;
            Bs[lk + 3][n] = v.w;
        }
        __syncthreads();

#pragma unroll 8
        for (int kk = 0; kk < 32; ++kk) {
            unsigned long long bv[4];
#pragma unroll
            for (int u = 0; u < 4; ++u)
                bv[u] = *(const unsigned long long*)&Bs[kk][c0 + 2 * u];
#pragma unroll
            for (int i = 0; i < 4; ++i) {
                float av = As[r0 + i][kk];
                unsigned long long ap = pack2(av, av);
#pragma unroll
                for (int u = 0; u < 4; ++u) fma2(acc[i][u], ap, bv[u]);
            }
        }
        __syncthreads();
    }

#pragma unroll
    for (int i = 0; i < 4; ++i) {
        int m = mbase + r0 + i;
        if (m < N_TOTAL) {
#pragma unroll
            for (int u = 0; u < 4; ++u) {
                float2 c = unpack2(acc[i][u]);
                c.x += b1[c0 + 2 * u];
                c.y += b1[c0 + 2 * u + 1];
                *(float2*)&g_x[(size_t)m * D + c0 + 2 * u] = c;
            }
        }
    }
}

// ===========================================================================
// Kernel 2: BatchNorm per micro-batch of 100 rows + fused y/a computation.
// grid = 100 blocks (one per batch), 128 threads (one per channel).
// ===========================================================================
__global__ void bn_kernel(const float* __restrict__ gamma,
                          const float* __restrict__ beta,
                          const float* __restrict__ sw,
                          float* __restrict__ outp) {
    const int b = blockIdx.x;
    const int c = threadIdx.x;
    __shared__ float arow[BSZ];
    if (c < BSZ) arow[c] = 0.f;

    const float* xb = g_x + (size_t)b * BSZ * D + c;
    float s = 0.f, s2 = 0.f;
    for (int r = 0; r < BSZ; ++r) {
        float v = xb[(size_t)r * D];
        s += v;
        s2 += v * v;
    }
    float mean = s * (1.f / BSZ);
    float var = s2 * (1.f / BSZ) - mean * mean;
    float rs = rsqrtf(var + 1e-5f);
    float g = gamma[c], be = beta[c], w = sw[c];
    __syncthreads();

    const int lane = c & 31;
    for (int r = 0; r < BSZ; ++r) {
        float v = xb[(size_t)r * D];
        float o = (v - mean) * rs * g + be;
        size_t idx = (size_t)(b * BSZ + r) * D + c;
        outp[idx] = o;
        g_y[idx] = -2.f * o * w;
        float contrib = w * o * o;
#pragma unroll
        for (int off = 16; off; off >>= 1)
            contrib += __shfl_down_sync(0xffffffffu, contrib, off);
        if (lane == 0) atomicAdd(&arow[r], contrib);
    }
    __syncthreads();
    if (c < BSZ) g_a[b * BSZ + c] = arow[c];
}

// ===========================================================================
// Kernel 3: scores[i,j] = relu(a_i + a_j + sb + y_i . out_j)
// (y already carries the -2*sw factor). M=N=10000, K=128.
// Tile 128x128, K-chunks of 32, 256 threads, 8x8 micro-tile (f32x2).
// ===========================================================================
__global__ void scores_kernel(const float* __restrict__ O,
                              const float* __restrict__ sbp) {
    __shared__ __align__(16) float As[128][36];
    __shared__ float Bs[32][132];

    const int tid = threadIdx.x;
    const int ibase = blockIdx.y * 128;
    const int jbase = blockIdx.x * 128;
    const int r0 = (tid >> 4) * 8;
    const int c0 = (tid & 15) * 8;

    unsigned long long acc[8][4];
#pragma unroll
    for (int i = 0; i < 8; ++i)
#pragma unroll
        for (int u = 0; u < 4; ++u) acc[i][u] = 0ULL;

    const int lr = tid >> 3;
    const int lk = (tid & 7) * 4;

    for (int kc = 0; kc < D; kc += 32) {
#pragma unroll
        for (int it = 0; it < 4; ++it) {
            int m = ibase + it * 32 + lr;
            float4 v = make_float4(0.f, 0.f, 0.f, 0.f);
            if (m < N_TOTAL)
                v = *(const float4*)&g_y[(size_t)m * D + kc + lk];
            *(float4*)&As[it * 32 + lr][lk] = v;
        }
#pragma unroll
        for (int it = 0; it < 4; ++it) {
            int j = jbase + it * 32 + lr;
            float4 v = make_float4(0.f, 0.f, 0.f, 0.f);
            if (j < N_TOTAL)
                v = *(const float4*)&O[(size_t)j * D + kc + lk];
            Bs[lk + 0][it * 32 + lr] = v.x;
            Bs[lk + 1][it * 32 + lr] = v.y;
            Bs[lk + 2][it * 32 + lr] = v.z;
            Bs[lk + 3][it * 32 + lr] = v.w;
        }
        __syncthreads();

#pragma unroll 4
        for (int kk = 0; kk < 32; ++kk) {
            unsigned long long bv[4];
#pragma unroll
            for (int u = 0; u < 4; ++u)
                bv[u] = *(const unsigned long long*)&Bs[kk][c0 + 2 * u];
#pragma unroll
            for (int i = 0; i < 8; ++i) {
                float av = As[r0 + i][kk];
                unsigned long long ap = pack2(av, av);
#pragma unroll
                for (int u = 0; u < 4; ++u) fma2(acc[i][u], ap, bv[u]);
            }
        }
        __syncthreads();
    }

    const float sbv = *sbp;
    float ai[8], aj[8];
#pragma unroll
    for (int i = 0; i < 8; ++i) {
        int gi = ibase + r0 + i;
        ai[i] = (gi < N_TOTAL) ? g_a[gi] : 0.f;
    }
#pragma unroll
    for (int t = 0; t < 8; ++t) {
        int gj = jbase + c0 + t;
        aj[t] = (gj < N_TOTAL) ? g_a[gj] : 0.f;
    }

#pragma unroll
    for (int i = 0; i < 8; ++i) {
        int gi = ibase + r0 + i;
        if (gi >= N_TOTAL) continue;
#pragma unroll
        for (int u = 0; u < 4; ++u) {
            int gj = jbase + c0 + 2 * u;
            if (gj >= N_TOTAL) continue;   // gj even, N even -> pair safe
            float2 c = unpack2(acc[i][u]);
            float base = ai[i] + sbv;
            float s0 = fmaxf(base + aj[2 * u] + c.x, 0.f);
            float s1 = fmaxf(base + aj[2 * u + 1] + c.y, 0.f);
            *(float2*)&g_scores[(size_t)gi * N_TOTAL + gj] = make_float2(s0, s1);
        }
    }
}

// ===========================================================================
// Kernel 4: per-row exact top-50 via 4-pass radix select on float bits
// (values >= 0 so uint order == float order), tie-break by lowest index
// (matches jax.lax.top_k stability). Softmax over the 50 values, scatter
// into the (zeroed) S row. One block per row.
// ===========================================================================
__global__ void topk_kernel(float* __restrict__ S) {
    __shared__ __align__(16) float srow[N_TOTAL];
    __shared__ unsigned hist[256];
    __shared__ int idxbuf[64];
    __shared__ int eqbuf[256];
    __shared__ float vbuf[TOPK];
    __shared__ float ebuf[TOPK];
    __shared__ int cnt_gt, cnt_eq;
    __shared__ unsigned sh_prefix;
    __shared__ int sh_krem;
    __shared__ float sh_inv;

    const int row = blockIdx.x;
    const int tid = threadIdx.x;
    const int nt = blockDim.x;

    const float4* rp = (const float4*)(g_scores + (size_t)row * N_TOTAL);
    float4* sp = (float4*)(S + (size_t)row * N_TOTAL);
    const float4 z = make_float4(0.f, 0.f, 0.f, 0.f);
    for (int i = tid; i < N_TOTAL / 4; i += nt) {
        ((float4*)srow)[i] = rp[i];
        sp[i] = z;
    }
    if (tid == 0) { cnt_gt = 0; cnt_eq = 0; }
    __syncthreads();

    unsigned prefix = 0;
    int krem = TOPK;
#pragma unroll
    for (int pass = 0; pass < 4; ++pass) {
        const int shift = 24 - pass * 8;
        for (int i = tid; i < 256; i += nt) hist[i] = 0;
        __syncthreads();
        const unsigned pm = pass ? (0xFFFFFFFFu << (shift + 8)) : 0u;
        for (int i = tid; i < N_TOTAL; i += nt) {
            unsigned b = __float_as_uint(srow[i]);
            if ((b & pm) == prefix) atomicAdd(&hist[(b >> shift) & 255], 1u);
        }
        __syncthreads();
        if (tid == 0) {
            unsigned cum = 0;
            int sel = 0;
            for (int bin = 255; bin >= 0; --bin) {
                unsigned h = hist[bin];
                if (cum + h >= (unsigned)krem) { sel = bin; break; }
                cum += h;
            }
            sh_prefix = prefix | ((unsigned)sel << shift);
            sh_krem = krem - (int)cum;
        }
        __syncthreads();
        prefix = sh_prefix;
        krem = sh_krem;
    }

    // prefix == bits of the 50th-largest value; krem == # equals still needed
    for (int i = tid; i < N_TOTAL; i += nt) {
        unsigned b = __float_as_uint(srow[i]);
        if (b > prefix) {
            int p = atomicAdd(&cnt_gt, 1);
            idxbuf[p] = i;                       // <= 49 guaranteed
        } else if (b == prefix) {
            int p = atomicAdd(&cnt_eq, 1);
            if (p < 256) eqbuf[p] = i;
        }
    }
    __syncthreads();

    if (tid == 0) {
        int n = cnt_gt;
        int need = TOPK - n;
        if (cnt_eq <= 256) {
            for (int t = 0; t < need; ++t) {     // lowest indices among ties
                int best = 0x7fffffff, bj = 0;
                for (int j2 = 0; j2 < cnt_eq; ++j2) {
                    int v = eqbuf[j2];
                    if (v < best) { best = v; bj = j2; }
                }
                idxbuf[n++] = best;
                eqbuf[bj] = 0x7fffffff;
            }
        } else {                                 // rare: massive tie bucket
            for (int i = 0; i < N_TOTAL && need > 0; ++i)
                if (__float_as_uint(srow[i]) == prefix) { idxbuf[n++] = i; --need; }
        }
    }
    __syncthreads();

    if (tid < TOPK) vbuf[tid] = srow[idxbuf[tid]];
    __syncthreads();
    if (tid == 0) {
        float mx = -1e30f;
        for (int t = 0; t < TOPK; ++t) mx = fmaxf(mx, vbuf[t]);
        float ssum = 0.f;
        for (int t = 0; t < TOPK; ++t) {
            float e = expf(vbuf[t] - mx);
            ebuf[t] = e;
            ssum += e;
        }
        sh_inv = 1.f / ssum;
    }
    __syncthreads();
    if (tid < TOPK)
        S[(size_t)row * N_TOTAL + idxbuf[tid]] = ebuf[tid] * sh_inv;
}

// ===========================================================================
extern "C" void kernel_launch(void* const* d_in, const int* in_sizes, int n_in,
                              void* d_out, int out_size) {
    const float* inputs = (const float*)d_in[0];
    const float* W1     = (const float*)d_in[1];
    const float* b1     = (const float*)d_in[2];
    const float* gamma  = (const float*)d_in[3];
    const float* beta   = (const float*)d_in[4];
    const float* sw     = (const float*)d_in[5];
    const float* sb     = (const float*)d_in[6];

    float* outp = (float*)d_out;                       // [10000,128] outputs
    float* Sp   = outp + (size_t)N_TOTAL * D;          // [10000,10000] S

    gemm1_kernel<<<(N_TOTAL + 63) / 64, 256>>>(inputs, W1, b1);
    bn_kernel<<<N_TOTAL / BSZ, D>>>(gamma, beta, sw, outp);
    dim3 sg((N_TOTAL + 127) / 128, (N_TOTAL + 127) / 128);
    scores_kernel<<<sg, 256>>>(outp, sb);
    topk_kernel<<<N_TOTAL, 256>>>(Sp);
}

// round 2
// speedup vs baseline: 1.3268x; 1.3268x over previous
#include <cuda_runtime.h>

#define N_TOTAL 10000
#define D 128
#define BSZ 100
#define FEAT 3072
#define TOPK 50
#define NTILES 79          // ceil(10000/128)
#define CAP 2048           // candidate buffer capacity in topk

// ---------------- scratch (device globals: no allocation allowed) ----------
__device__ float g_x[(size_t)N_TOTAL * D];                 // pre-BN linear out
__device__ float g_y[(size_t)N_TOTAL * D];                 // -2 * out * sw
__device__ float g_a[N_TOTAL];                             // sum_k sw*out^2
__device__ float g_scores[(size_t)N_TOTAL * N_TOTAL];      // 400 MB scratch

// ---------------- f32x2 helpers (packed FFMA2) -----------------------------
__device__ __forceinline__ unsigned long long pack2(float x, float y) {
    unsigned long long r;
    asm("mov.b64 %0, {%1, %2};" : "=l"(r) : "f"(x), "f"(y));
    return r;
}
__device__ __forceinline__ float2 unpack2(unsigned long long v) {
    float x, y;
    asm("mov.b64 {%0, %1}, %2;" : "=f"(x), "=f"(y) : "l"(v));
    return make_float2(x, y);
}
__device__ __forceinline__ void fma2(unsigned long long& c,
                                     unsigned long long a,
                                     unsigned long long b) {
    asm("fma.rn.f32x2 %0, %1, %2, %3;" : "=l"(c) : "l"(a), "l"(b), "l"(c));
}

// ===========================================================================
// Kernel 1: x = inputs @ W1^T + b1      (M=10000, N=128, K=3072)
// ===========================================================================
__global__ void gemm1_kernel(const float* __restrict__ A,
                             const float* __restrict__ W,
                             const float* __restrict__ b1) {
    __shared__ __align__(16) float As[64][36];
    __shared__ float Bs[32][132];

    const int tid = threadIdx.x;
    const int mbase = blockIdx.x * 64;
    const int r0 = (tid >> 4) * 4;
    const int c0 = (tid & 15) * 8;

    unsigned long long acc[4][4];
#pragma unroll
    for (int i = 0; i < 4; ++i)
#pragma unroll
        for (int u = 0; u < 4; ++u) acc[i][u] = 0ULL;

    const int lr = tid >> 3;
    const int lk = (tid & 7) * 4;

    for (int kc = 0; kc < FEAT; kc += 32) {
#pragma unroll
        for (int it = 0; it < 2; ++it) {
            int m = mbase + it * 32 + lr;
            float4 v = make_float4(0.f, 0.f, 0.f, 0.f);
            if (m < N_TOTAL)
                v = *(const float4*)&A[(size_t)m * FEAT + kc + lk];
            *(float4*)&As[it * 32 + lr][lk] = v;
        }
#pragma unroll
        for (int it = 0; it < 4; ++it) {
            int n = it * 32 + lr;
            float4 v = *(const float4*)&W[(size_t)n * FEAT + kc + lk];
            Bs[lk + 0][n] = v.x;
            Bs[lk + 1][n] = v.y;
            Bs[lk + 2][n] = v.z;
            Bs[lk + 3][n] = v.w;
        }
        __syncthreads();

#pragma unroll 8
        for (int kk = 0; kk < 32; ++kk) {
            unsigned long long bv[4];
#pragma unroll
            for (int u = 0; u < 4; ++u)
                bv[u] = *(const unsigned long long*)&Bs[kk][c0 + 2 * u];
#pragma unroll
            for (int i = 0; i < 4; ++i) {
                float av = As[r0 + i][kk];
                unsigned long long ap = pack2(av, av);
#pragma unroll
                for (int u = 0; u < 4; ++u) fma2(acc[i][u], ap, bv[u]);
            }
        }
        __syncthreads();
    }

#pragma unroll
    for (int i = 0; i < 4; ++i) {
        int m = mbase + r0 + i;
        if (m < N_TOTAL) {
#pragma unroll
            for (int u = 0; u < 4; ++u) {
                float2 c = unpack2(acc[i][u]);
                c.x += b1[c0 + 2 * u];
                c.y += b1[c0 + 2 * u + 1];
                *(float2*)&g_x[(size_t)m * D + c0 + 2 * u] = c;
            }
        }
    }
}

// ===========================================================================
// Kernel 2: BatchNorm per micro-batch of 100 rows + fused y/a computation.
// ===========================================================================
__global__ void bn_kernel(const float* __restrict__ gamma,
                          const float* __restrict__ beta,
                          const float* __restrict__ sw,
                          float* __restrict__ outp) {
    const int b = blockIdx.x;
    const int c = threadIdx.x;
    __shared__ float arow[BSZ];
    if (c < BSZ) arow[c] = 0.f;

    const float* xb = g_x + (size_t)b * BSZ * D + c;
    float s = 0.f, s2 = 0.f;
    for (int r = 0; r < BSZ; ++r) {
        float v = xb[(size_t)r * D];
        s += v;
        s2 += v * v;
    }
    float mean = s * (1.f / BSZ);
    float var = s2 * (1.f / BSZ) - mean * mean;
    float rs = rsqrtf(var + 1e-5f);
    float g = gamma[c], be = beta[c], w = sw[c];
    __syncthreads();

    const int lane = c & 31;
    for (int r = 0; r < BSZ; ++r) {
        float v = xb[(size_t)r * D];
        float o = (v - mean) * rs * g + be;
        size_t idx = (size_t)(b * BSZ + r) * D + c;
        outp[idx] = o;
        g_y[idx] = -2.f * o * w;
        float contrib = w * o * o;
#pragma unroll
        for (int off = 16; off; off >>= 1)
            contrib += __shfl_down_sync(0xffffffffu, contrib, off);
        if (lane == 0) atomicAdd(&arow[r], contrib);
    }
    __syncthreads();
    if (c < BSZ) g_a[b * BSZ + c] = arow[c];
}

// ===========================================================================
// Kernel 3: scores[i,j] = relu(a_i + a_j + sb + y_i . out_j)   (SYMMETRIC)
// Only upper-triangular 128x128 tiles computed; mirror tile written too.
// ===========================================================================
__global__ void scores_kernel(const float* __restrict__ O,
                              const float* __restrict__ sbp) {
    const int bi = blockIdx.y;
    const int bj = blockIdx.x;
    if (bi > bj) return;

    __shared__ __align__(16) float As[128][36];
    __shared__ float Bs[32][132];

    const int tid = threadIdx.x;
    const int ibase = bi * 128;
    const int jbase = bj * 128;
    const int r0 = (tid >> 4) * 8;
    const int c0 = (tid & 15) * 8;

    unsigned long long acc[8][4];
#pragma unroll
    for (int i = 0; i < 8; ++i)
#pragma unroll
        for (int u = 0; u < 4; ++u) acc[i][u] = 0ULL;

    const int lr = tid >> 3;
    const int lk = (tid & 7) * 4;

    for (int kc = 0; kc < D; kc += 32) {
#pragma unroll
        for (int it = 0; it < 4; ++it) {
            int m = ibase + it * 32 + lr;
            float4 v = make_float4(0.f, 0.f, 0.f, 0.f);
            if (m < N_TOTAL)
                v = *(const float4*)&g_y[(size_t)m * D + kc + lk];
            *(float4*)&As[it * 32 + lr][lk] = v;
        }
#pragma unroll
        for (int it = 0; it < 4; ++it) {
            int j = jbase + it * 32 + lr;
            float4 v = make_float4(0.f, 0.f, 0.f, 0.f);
            if (j < N_TOTAL)
                v = *(const float4*)&O[(size_t)j * D + kc + lk];
            Bs[lk + 0][it * 32 + lr] = v.x;
            Bs[lk + 1][it * 32 + lr] = v.y;
            Bs[lk + 2][it * 32 + lr] = v.z;
            Bs[lk + 3][it * 32 + lr] = v.w;
        }
        __syncthreads();

#pragma unroll 4
        for (int kk = 0; kk < 32; ++kk) {
            unsigned long long bv[4];
#pragma unroll
            for (int u = 0; u < 4; ++u)
                bv[u] = *(const unsigned long long*)&Bs[kk][c0 + 2 * u];
#pragma unroll
            for (int i = 0; i < 8; ++i) {
                float av = As[r0 + i][kk];
                unsigned long long ap = pack2(av, av);
#pragma unroll
                for (int u = 0; u < 4; ++u) fma2(acc[i][u], ap, bv[u]);
            }
        }
        __syncthreads();
    }

    const float sbv = *sbp;
    float ai[8], aj[8];
#pragma unroll
    for (int i = 0; i < 8; ++i) {
        int gi = ibase + r0 + i;
        ai[i] = (gi < N_TOTAL) ? g_a[gi] : 0.f;
    }
#pragma unroll
    for (int t = 0; t < 8; ++t) {
        int gj = jbase + c0 + t;
        aj[t] = (gj < N_TOTAL) ? g_a[gj] : 0.f;
    }

    // relu'd score values for this thread's 8x8 micro-tile
    float sv[8][8];
#pragma unroll
    for (int i = 0; i < 8; ++i) {
        float base = ai[i] + sbv;
#pragma unroll
        for (int u = 0; u < 4; ++u) {
            float2 c = unpack2(acc[i][u]);
            sv[i][2 * u]     = fmaxf(base + aj[2 * u] + c.x, 0.f);
            sv[i][2 * u + 1] = fmaxf(base + aj[2 * u + 1] + c.y, 0.f);
        }
    }

    const bool full_i = (ibase + 128 <= N_TOTAL);
    const bool full_j = (jbase + 128 <= N_TOTAL);

    if (full_i && full_j) {
        // normal tile: two float4 stores per row
#pragma unroll
        for (int i = 0; i < 8; ++i) {
            size_t base = (size_t)(ibase + r0 + i) * N_TOTAL + jbase + c0;
            *(float4*)&g_scores[base]     = make_float4(sv[i][0], sv[i][1], sv[i][2], sv[i][3]);
            *(float4*)&g_scores[base + 4] = make_float4(sv[i][4], sv[i][5], sv[i][6], sv[i][7]);
        }
        if (bi != bj) {
            // mirror tile: transpose from registers
#pragma unroll
            for (int j = 0; j < 8; ++j) {
                size_t base = (size_t)(jbase + c0 + j) * N_TOTAL + ibase + r0;
                *(float4*)&g_scores[base]     = make_float4(sv[0][j], sv[1][j], sv[2][j], sv[3][j]);
                *(float4*)&g_scores[base + 4] = make_float4(sv[4][j], sv[5][j], sv[6][j], sv[7][j]);
            }
        }
    } else {
        // partial tile: scalar guarded stores
#pragma unroll
        for (int i = 0; i < 8; ++i) {
            int gi = ibase + r0 + i;
            if (gi >= N_TOTAL) continue;
#pragma unroll
            for (int j = 0; j < 8; ++j) {
                int gj = jbase + c0 + j;
                if (gj >= N_TOTAL) continue;
                g_scores[(size_t)gi * N_TOTAL + gj] = sv[i][j];
                if (bi != bj)
                    g_scores[(size_t)gj * N_TOTAL + gi] = sv[i][j];
            }
        }
    }
}

// ===========================================================================
// Kernel 4: per-row exact top-50.
//   pass 0: stream row from DRAM once (also zero S), 256-bin MSB histogram.
//   Collect the threshold bin's values into a shared candidate buffer
//   (cap 2048) and finish the byte-radix locally. If the bin overflows,
//   continue byte-level passes from the (L2-hot) global row.
//   Exact tie-break: lowest index among equal values (matches lax.top_k).
// ===========================================================================
__global__ void topk_kernel(float* __restrict__ S) {
    __shared__ unsigned hist[256];
    __shared__ float cval[CAP];
    __shared__ int   cidx[CAP];
    __shared__ int idxbuf[64];
    __shared__ int eqbuf[256];
    __shared__ float vbuf[TOPK];
    __shared__ float ebuf[TOPK];
    __shared__ int cnt_gt, cnt_eq, cnt_c;
    __shared__ unsigned sh_prefix;
    __shared__ int sh_krem, sh_binc;
    __shared__ float sh_inv;

    const int row = blockIdx.x;
    const int tid = threadIdx.x;
    const int nt = blockDim.x;

    const float* rowp = g_scores + (size_t)row * N_TOTAL;
    const float4* rp4 = (const float4*)rowp;
    float4* sp4 = (float4*)(S + (size_t)row * N_TOTAL);

    for (int i = tid; i < 256; i += nt) hist[i] = 0;
    if (tid == 0) { cnt_gt = 0; cnt_eq = 0; cnt_c = 0; }
    __syncthreads();

    // ---- pass 0: zero S + MSB-byte histogram (single DRAM stream) ----
    const float4 z = make_float4(0.f, 0.f, 0.f, 0.f);
    for (int i = tid; i < N_TOTAL / 4; i += nt) {
        float4 v = rp4[i];
        sp4[i] = z;
        atomicAdd(&hist[__float_as_uint(v.x) >> 24], 1u);
        atomicAdd(&hist[__float_as_uint(v.y) >> 24], 1u);
        atomicAdd(&hist[__float_as_uint(v.z) >> 24], 1u);
        atomicAdd(&hist[__float_as_uint(v.w) >> 24], 1u);
    }
    __syncthreads();

    unsigned prefix = 0;
    int krem = TOPK;
    int shift = 24;
    int collected = 0;

    for (int pass = 0; pass < 4; ++pass) {
        if (pass > 0) {
            for (int i = tid; i < 256; i += nt) hist[i] = 0;
            __syncthreads();
            const int ps = shift + 8;
            const unsigned pp = prefix >> ps;
            for (int i = tid; i < N_TOTAL; i += nt) {
                unsigned b = __float_as_uint(rowp[i]);
                if ((b >> ps) == pp) atomicAdd(&hist[(b >> shift) & 255], 1u);
            }
            __syncthreads();
        }
        if (tid == 0) {
            unsigned cum = 0;
            int sel = 0;
            for (int bin = 255; bin >= 0; --bin) {
                unsigned h = hist[bin];
                if (cum + h >= (unsigned)krem) { sel = bin; break; }
                cum += h;
            }
            sh_prefix = prefix | ((unsigned)sel << shift);
            sh_krem = krem - (int)cum;
            sh_binc = (int)hist[sel];
        }
        __syncthreads();
        prefix = sh_prefix;
        krem = sh_krem;
        const int binc = sh_binc;
        shift -= 8;

        if (shift >= 0 && binc <= CAP) {
            // collect: strictly-greater -> idxbuf (<=49), equal-bin -> cands
            const int gs = shift + 8;
            const unsigned tp = prefix >> gs;
            for (int i = tid; i < N_TOTAL; i += nt) {
                unsigned b = __float_as_uint(rowp[i]);
                unsigned hp = b >> gs;
                if (hp > tp) {
                    int p = atomicAdd(&cnt_gt, 1);
                    idxbuf[p] = i;
                } else if (hp == tp) {
                    int p = atomicAdd(&cnt_c, 1);
                    cval[p] = __uint_as_float(b);
                    cidx[p] = i;
                }
            }
            __syncthreads();
            collected = 1;
            break;
        }
    }

    if (collected) {
        const int nc = cnt_c;
        // finish the radix over the shared candidate buffer
        while (shift >= 0) {
            for (int i = tid; i < 256; i += nt) hist[i] = 0;
            __syncthreads();
            const int ps = shift + 8;
            const unsigned pp = prefix >> ps;
            for (int i = tid; i < nc; i += nt) {
                unsigned b = __float_as_uint(cval[i]);
                if ((b >> ps) == pp) atomicAdd(&hist[(b >> shift) & 255], 1u);
            }
            __syncthreads();
            if (tid == 0) {
                unsigned cum = 0;
                int sel = 0;
                for (int bin = 255; bin >= 0; --bin) {
                    unsigned h = hist[bin];
                    if (cum + h >= (unsigned)krem) { sel = bin; break; }
                    cum += h;
                }
                sh_prefix = prefix | ((unsigned)sel << shift);
                sh_krem = krem - (int)cum;
            }
            __syncthreads();
            prefix = sh_prefix;
            krem = sh_krem;
            shift -= 8;
        }
        // emit from candidates against the exact threshold bits
        for (int i = tid; i < nc; i += nt) {
            unsigned b = __float_as_uint(cval[i]);
            if (b > prefix) {
                int p = atomicAdd(&cnt_gt, 1);
                idxbuf[p] = cidx[i];
            } else if (b == prefix) {
                int p = atomicAdd(&cnt_eq, 1);
                if (p < 256) eqbuf[p] = cidx[i];
            }
        }
        __syncthreads();
    } else {
        // all 4 passes ran from global; prefix is the exact threshold bits
        for (int i = tid; i < N_TOTAL; i += nt) {
            unsigned b = __float_as_uint(rowp[i]);
            if (b > prefix) {
                int p = atomicAdd(&cnt_gt, 1);
                idxbuf[p] = i;
            } else if (b == prefix) {
                int p = atomicAdd(&cnt_eq, 1);
                if (p < 256) eqbuf[p] = i;
            }
        }
        __syncthreads();
    }

    // ---- choose krem lowest-index ties, softmax, scatter ----
    if (tid == 0) {
        int n = cnt_gt;
        int need = TOPK - n;
        if (cnt_eq <= 256) {
            for (int t = 0; t < need; ++t) {
                int best = 0x7fffffff, bj2 = 0;
                for (int j2 = 0; j2 < cnt_eq; ++j2) {
                    int v = eqbuf[j2];
                    if (v < best) { best = v; bj2 = j2; }
                }
                idxbuf[n++] = best;
                eqbuf[bj2] = 0x7fffffff;
            }
        } else {
            for (int i = 0; i < N_TOTAL && need > 0; ++i)
                if (__float_as_uint(rowp[i]) == prefix) { idxbuf[n++] = i; --need; }
        }
    }
    __syncthreads();

    if (tid < TOPK) vbuf[tid] = rowp[idxbuf[tid]];
    __syncthreads();
    if (tid == 0) {
        float mx = -1e30f;
        for (int t = 0; t < TOPK; ++t) mx = fmaxf(mx, vbuf[t]);
        float ssum = 0.f;
        for (int t = 0; t < TOPK; ++t) {
            float e = expf(vbuf[t] - mx);
            ebuf[t] = e;
            ssum += e;
        }
        sh_inv = 1.f / ssum;
    }
    __syncthreads();
    if (tid < TOPK)
        S[(size_t)row * N_TOTAL + idxbuf[tid]] = ebuf[tid] * sh_inv;
}

// ===========================================================================
extern "C" void kernel_launch(void* const* d_in, const int* in_sizes, int n_in,
                              void* d_out, int out_size) {
    const float* inputs = (const float*)d_in[0];
    const float* W1     = (const float*)d_in[1];
    const float* b1     = (const float*)d_in[2];
    const float* gamma  = (const float*)d_in[3];
    const float* beta   = (const float*)d_in[4];
    const float* sw     = (const float*)d_in[5];
    const float* sb     = (const float*)d_in[6];

    float* outp = (float*)d_out;                       // [10000,128] outputs
    float* Sp   = outp + (size_t)N_TOTAL * D;          // [10000,10000] S

    gemm1_kernel<<<(N_TOTAL + 63) / 64, 256>>>(inputs, W1, b1);
    bn_kernel<<<N_TOTAL / BSZ, D>>>(gamma, beta, sw, outp);
    dim3 sg(NTILES, NTILES);
    scores_kernel<<<sg, 256>>>(outp, sb);
    topk_kernel<<<N_TOTAL, 256>>>(Sp);
}

// round 3
// speedup vs baseline: 1.3855x; 1.0442x over previous
#include <cuda_runtime.h>

#define N_TOTAL 10000
#define D 128
#define BSZ 100
#define FEAT 3072
#define TOPK 50
#define NTILES 79          // ceil(10000/128)
#define TRI_BLOCKS (NTILES * (NTILES + 1) / 2)
#define CAP 2048           // candidate buffer capacity in topk
#define NF4 2500           // N_TOTAL/4

// ---------------- scratch (device globals: no allocation allowed) ----------
__device__ float g_x[(size_t)N_TOTAL * D];                 // pre-BN linear out
__device__ float g_y[(size_t)N_TOTAL * D];                 // -2 * out * sw
__device__ float g_a[N_TOTAL];                             // sum_k sw*out^2
__device__ float g_scores[(size_t)N_TOTAL * N_TOTAL];      // 400 MB scratch

// ---------------- f32x2 helpers (packed FFMA2) -----------------------------
__device__ __forceinline__ unsigned long long pack2(float x, float y) {
    unsigned long long r;
    asm("mov.b64 %0, {%1, %2};" : "=l"(r) : "f"(x), "f"(y));
    return r;
}
__device__ __forceinline__ float2 unpack2(unsigned long long v) {
    float x, y;
    asm("mov.b64 {%0, %1}, %2;" : "=f"(x), "=f"(y) : "l"(v));
    return make_float2(x, y);
}
__device__ __forceinline__ void fma2(unsigned long long& c,
                                     unsigned long long a,
                                     unsigned long long b) {
    asm("fma.rn.f32x2 %0, %1, %2, %3;" : "=l"(c) : "l"(a), "l"(b), "l"(c));
}

// ===========================================================================
// Kernel 1: x = inputs @ W1^T + b1      (M=10000, N=128, K=3072)
// ===========================================================================
__global__ void gemm1_kernel(const float* __restrict__ A,
                             const float* __restrict__ W,
                             const float* __restrict__ b1) {
    __shared__ __align__(16) float As[64][36];
    __shared__ float Bs[32][132];

    const int tid = threadIdx.x;
    const int mbase = blockIdx.x * 64;
    const int r0 = (tid >> 4) * 4;
    const int c0 = (tid & 15) * 8;

    unsigned long long acc[4][4];
#pragma unroll
    for (int i = 0; i < 4; ++i)
#pragma unroll
        for (int u = 0; u < 4; ++u) acc[i][u] = 0ULL;

    const int lr = tid >> 3;
    const int lk = (tid & 7) * 4;

    for (int kc = 0; kc < FEAT; kc += 32) {
#pragma unroll
        for (int it = 0; it < 2; ++it) {
            int m = mbase + it * 32 + lr;
            float4 v = make_float4(0.f, 0.f, 0.f, 0.f);
            if (m < N_TOTAL)
                v = *(const float4*)&A[(size_t)m * FEAT + kc + lk];
            *(float4*)&As[it * 32 + lr][lk] = v;
        }
#pragma unroll
        for (int it = 0; it < 4; ++it) {
            int n = it * 32 + lr;
            float4 v = *(const float4*)&W[(size_t)n * FEAT + kc + lk];
            Bs[lk + 0][n] = v.x;
            Bs[lk + 1][n] = v.y;
            Bs[lk + 2][n] = v.z;
            Bs[lk + 3][n] = v.w;
        }
        __syncthreads();

#pragma unroll 8
        for (int kk = 0; kk < 32; ++kk) {
            unsigned long long bv[4];
#pragma unroll
            for (int u = 0; u < 4; ++u)
                bv[u] = *(const unsigned long long*)&Bs[kk][c0 + 2 * u];
#pragma unroll
            for (int i = 0; i < 4; ++i) {
                float av = As[r0 + i][kk];
                unsigned long long ap = pack2(av, av);
#pragma unroll
                for (int u = 0; u < 4; ++u) fma2(acc[i][u], ap, bv[u]);
            }
        }
        __syncthreads();
    }

#pragma unroll
    for (int i = 0; i < 4; ++i) {
        int m = mbase + r0 + i;
        if (m < N_TOTAL) {
#pragma unroll
            for (int u = 0; u < 4; ++u) {
                float2 c = unpack2(acc[i][u]);
                c.x += b1[c0 + 2 * u];
                c.y += b1[c0 + 2 * u + 1];
                *(float2*)&g_x[(size_t)m * D + c0 + 2 * u] = c;
            }
        }
    }
}

// ===========================================================================
// Kernel 2: BatchNorm per micro-batch of 100 rows + fused y/a computation.
// ===========================================================================
__global__ void bn_kernel(const float* __restrict__ gamma,
                          const float* __restrict__ beta,
                          const float* __restrict__ sw,
                          float* __restrict__ outp) {
    const int b = blockIdx.x;
    const int c = threadIdx.x;
    __shared__ float arow[BSZ];
    if (c < BSZ) arow[c] = 0.f;

    const float* xb = g_x + (size_t)b * BSZ * D + c;
    float s = 0.f, s2 = 0.f;
    for (int r = 0; r < BSZ; ++r) {
        float v = xb[(size_t)r * D];
        s += v;
        s2 += v * v;
    }
    float mean = s * (1.f / BSZ);
    float var = s2 * (1.f / BSZ) - mean * mean;
    float rs = rsqrtf(var + 1e-5f);
    float g = gamma[c], be = beta[c], w = sw[c];
    __syncthreads();

    const int lane = c & 31;
    for (int r = 0; r < BSZ; ++r) {
        float v = xb[(size_t)r * D];
        float o = (v - mean) * rs * g + be;
        size_t idx = (size_t)(b * BSZ + r) * D + c;
        outp[idx] = o;
        g_y[idx] = -2.f * o * w;
        float contrib = w * o * o;
#pragma unroll
        for (int off = 16; off; off >>= 1)
            contrib += __shfl_down_sync(0xffffffffu, contrib, off);
        if (lane == 0) atomicAdd(&arow[r], contrib);
    }
    __syncthreads();
    if (c < BSZ) g_a[b * BSZ + c] = arow[c];
}

// ===========================================================================
// Kernel 3: scores[i,j] = relu(a_i + a_j + sb + y_i . out_j)   (SYMMETRIC)
// Triangular launch: only 3160 upper-tri tiles; mirror tile written too.
// ===========================================================================
__global__ void scores_kernel(const float* __restrict__ O,
                              const float* __restrict__ sbp) {
    // map linear block id -> (bi, bj), bi <= bj, row-major over upper triangle
    int t = blockIdx.x;
    int bi = 0;
    while (t >= NTILES - bi) { t -= NTILES - bi; ++bi; }
    const int bj = bi + t;

    __shared__ __align__(16) float As[128][36];
    __shared__ float Bs[32][132];

    const int tid = threadIdx.x;
    const int ibase = bi * 128;
    const int jbase = bj * 128;
    const int r0 = (tid >> 4) * 8;
    const int c0 = (tid & 15) * 8;

    unsigned long long acc[8][4];
#pragma unroll
    for (int i = 0; i < 8; ++i)
#pragma unroll
        for (int u = 0; u < 4; ++u) acc[i][u] = 0ULL;

    const int lr = tid >> 3;
    const int lk = (tid & 7) * 4;

    for (int kc = 0; kc < D; kc += 32) {
#pragma unroll
        for (int it = 0; it < 4; ++it) {
            int m = ibase + it * 32 + lr;
            float4 v = make_float4(0.f, 0.f, 0.f, 0.f);
            if (m < N_TOTAL)
                v = *(const float4*)&g_y[(size_t)m * D + kc + lk];
            *(float4*)&As[it * 32 + lr][lk] = v;
        }
#pragma unroll
        for (int it = 0; it < 4; ++it) {
            int j = jbase + it * 32 + lr;
            float4 v = make_float4(0.f, 0.f, 0.f, 0.f);
            if (j < N_TOTAL)
                v = *(const float4*)&O[(size_t)j * D + kc + lk];
            Bs[lk + 0][it * 32 + lr] = v.x;
            Bs[lk + 1][it * 32 + lr] = v.y;
            Bs[lk + 2][it * 32 + lr] = v.z;
            Bs[lk + 3][it * 32 + lr] = v.w;
        }
        __syncthreads();

#pragma unroll 4
        for (int kk = 0; kk < 32; ++kk) {
            unsigned long long bv[4];
#pragma unroll
            for (int u = 0; u < 4; ++u)
                bv[u] = *(const unsigned long long*)&Bs[kk][c0 + 2 * u];
#pragma unroll
            for (int i = 0; i < 8; ++i) {
                float av = As[r0 + i][kk];
                unsigned long long ap = pack2(av, av);
#pragma unroll
                for (int u = 0; u < 4; ++u) fma2(acc[i][u], ap, bv[u]);
            }
        }
        __syncthreads();
    }

    const float sbv = *sbp;
    float ai[8], aj[8];
#pragma unroll
    for (int i = 0; i < 8; ++i) {
        int gi = ibase + r0 + i;
        ai[i] = (gi < N_TOTAL) ? g_a[gi] : 0.f;
    }
#pragma unroll
    for (int t2 = 0; t2 < 8; ++t2) {
        int gj = jbase + c0 + t2;
        aj[t2] = (gj < N_TOTAL) ? g_a[gj] : 0.f;
    }

    float sv[8][8];
#pragma unroll
    for (int i = 0; i < 8; ++i) {
        float base = ai[i] + sbv;
#pragma unroll
        for (int u = 0; u < 4; ++u) {
            float2 c = unpack2(acc[i][u]);
            sv[i][2 * u]     = fmaxf(base + aj[2 * u] + c.x, 0.f);
            sv[i][2 * u + 1] = fmaxf(base + aj[2 * u + 1] + c.y, 0.f);
        }
    }

    const bool full_i = (ibase + 128 <= N_TOTAL);
    const bool full_j = (jbase + 128 <= N_TOTAL);

    if (full_i && full_j) {
#pragma unroll
        for (int i = 0; i < 8; ++i) {
            size_t base = (size_t)(ibase + r0 + i) * N_TOTAL + jbase + c0;
            *(float4*)&g_scores[base]     = make_float4(sv[i][0], sv[i][1], sv[i][2], sv[i][3]);
            *(float4*)&g_scores[base + 4] = make_float4(sv[i][4], sv[i][5], sv[i][6], sv[i][7]);
        }
        if (bi != bj) {
#pragma unroll
            for (int j = 0; j < 8; ++j) {
                size_t base = (size_t)(jbase + c0 + j) * N_TOTAL + ibase + r0;
                *(float4*)&g_scores[base]     = make_float4(sv[0][j], sv[1][j], sv[2][j], sv[3][j]);
                *(float4*)&g_scores[base + 4] = make_float4(sv[4][j], sv[5][j], sv[6][j], sv[7][j]);
            }
        }
    } else {
#pragma unroll
        for (int i = 0; i < 8; ++i) {
            int gi = ibase + r0 + i;
            if (gi >= N_TOTAL) continue;
#pragma unroll
            for (int j = 0; j < 8; ++j) {
                int gj = jbase + c0 + j;
                if (gj >= N_TOTAL) continue;
                g_scores[(size_t)gi * N_TOTAL + gj] = sv[i][j];
                if (bi != bj)
                    g_scores[(size_t)gj * N_TOTAL + gi] = sv[i][j];
            }
        }
    }
}

// ===========================================================================
// Kernel 4: per-row exact top-50.
//   - row held in registers (10 float4 / thread)
//   - per-warp private MSB histograms (no inter-warp atomic contention)
//   - warp-0 shfl-based suffix-scan bin selection (no serial 256-loop)
//   - candidate buffer finish; global fallback if threshold bin > CAP
// ===========================================================================
__global__ void __launch_bounds__(256) topk_kernel(float* __restrict__ S) {
    __shared__ unsigned whist[8][256];
    __shared__ unsigned hist[256];
    __shared__ float cval[CAP];
    __shared__ int   cidx[CAP];
    __shared__ int idxbuf[64];
    __shared__ int eqbuf[256];
    __shared__ float vbuf[TOPK];
    __shared__ float ebuf[TOPK];
    __shared__ int cnt_gt, cnt_eq, cnt_c;
    __shared__ unsigned sh_sel;
    __shared__ int sh_krem, sh_binc;
    __shared__ float sh_inv;

    const int row = blockIdx.x;
    const int tid = threadIdx.x;
    const int warp = tid >> 5;
    const int lane = tid & 31;

    const float* rowp = g_scores + (size_t)row * N_TOTAL;
    const float4* rp4 = (const float4*)rowp;
    float4* sp4 = (float4*)(S + (size_t)row * N_TOTAL);

    for (int i = tid; i < 2048; i += 256) ((unsigned*)whist)[i] = 0;
    if (tid == 0) { cnt_gt = 0; cnt_eq = 0; cnt_c = 0; }
    __syncthreads();

    // ---- pass 0: load row into regs, zero S, per-warp MSB histogram ----
    const float4 z = make_float4(0.f, 0.f, 0.f, 0.f);
    float4 v[10];
#pragma unroll
    for (int it = 0; it < 10; ++it) {
        int i4 = it * 256 + tid;
        if (i4 < NF4) {
            float4 val = rp4[i4];
            v[it] = val;
            sp4[i4] = z;
            atomicAdd(&whist[warp][__float_as_uint(val.x) >> 24], 1u);
            atomicAdd(&whist[warp][__float_as_uint(val.y) >> 24], 1u);
            atomicAdd(&whist[warp][__float_as_uint(val.z) >> 24], 1u);
            atomicAdd(&whist[warp][__float_as_uint(val.w) >> 24], 1u);
        }
    }
    __syncthreads();

    // reduce per-warp hists
    {
        unsigned hsum = 0;
#pragma unroll
        for (int w = 0; w < 8; ++w) hsum += whist[w][tid];
        hist[tid] = hsum;
    }
    __syncthreads();

    // ---- warp-0 bin selection helper (inlined via lambda-like macro) ----
    // finds largest bin b with suffix_count(b) >= krem; writes sel/krem'/binc
#define WARP_SELECT(KREM)                                                     \
    if (tid < 32) {                                                           \
        unsigned h[8], ls[8];                                                 \
        int b0 = lane * 8;                                                    \
        _Pragma("unroll")                                                     \
        for (int j = 0; j < 8; ++j) h[j] = hist[b0 + j];                      \
        ls[7] = h[7];                                                         \
        _Pragma("unroll")                                                     \
        for (int j = 6; j >= 0; --j) ls[j] = ls[j + 1] + h[j];                \
        unsigned tot = ls[0];                                                 \
        unsigned ss = tot;                                                    \
        _Pragma("unroll")                                                     \
        for (int off = 1; off < 32; off <<= 1) {                              \
            unsigned o = __shfl_down_sync(0xffffffffu, ss, off);              \
            if (lane + off < 32) ss += o;                                     \
        }                                                                     \
        unsigned above = ss - tot;                                            \
        int best = -1;                                                        \
        _Pragma("unroll")                                                     \
        for (int j = 7; j >= 0; --j)                                          \
            if (best < 0 && above + ls[j] >= (unsigned)(KREM)) best = j;      \
        unsigned m = __ballot_sync(0xffffffffu, best >= 0);                   \
        int hi = 31 - __clz((int)m);                                          \
        if (lane == hi) {                                                     \
            unsigned Sb = above + ls[best];                                   \
            sh_sel = (unsigned)(b0 + best);                                   \
            sh_binc = (int)h[best];                                           \
            sh_krem = (KREM) - (int)(Sb - h[best]);                           \
        }                                                                     \
    }

    WARP_SELECT(TOPK)
    __syncthreads();

    unsigned prefix = sh_sel << 24;
    int krem = sh_krem;
    const int binc = sh_binc;
    const unsigned sel0 = sh_sel;

    if (binc <= CAP) {
        // collect from registers: bins > sel0 -> winners; == sel0 -> candidates
#pragma unroll
        for (int it = 0; it < 10; ++it) {
            int i4 = it * 256 + tid;
            if (i4 < NF4) {
                float4 val = v[it];
                unsigned b0_ = __float_as_uint(val.x);
                unsigned b1_ = __float_as_uint(val.y);
                unsigned b2_ = __float_as_uint(val.z);
                unsigned b3_ = __float_as_uint(val.w);
#define COLLECT(B, IDX)                                                       \
                {                                                             \
                    unsigned hp = (B) >> 24;                                  \
                    if (hp > sel0) {                                          \
                        int p = atomicAdd(&cnt_gt, 1);                        \
                        idxbuf[p] = (IDX);                                    \
                    } else if (hp == sel0) {                                  \
                        int p = atomicAdd(&cnt_c, 1);                         \
                        cval[p] = __uint_as_float(B);                         \
                        cidx[p] = (IDX);                                      \
                    }                                                         \
                }
                COLLECT(b0_, 4 * i4 + 0)
                COLLECT(b1_, 4 * i4 + 1)
                COLLECT(b2_, 4 * i4 + 2)
                COLLECT(b3_, 4 * i4 + 3)
#undef COLLECT
            }
        }
        __syncthreads();
        const int nc = cnt_c;

        // finish radix over shared candidates
        for (int shift = 16; shift >= 0; shift -= 8) {
            hist[tid] = 0;
            __syncthreads();
            const int ps = shift + 8;
            const unsigned pp = prefix >> ps;
            for (int i = tid; i < nc; i += 256) {
                unsigned b = __float_as_uint(cval[i]);
                if ((b >> ps) == pp) atomicAdd(&hist[(b >> shift) & 255], 1u);
            }
            __syncthreads();
            WARP_SELECT(krem)
            __syncthreads();
            prefix |= sh_sel << shift;
            krem = sh_krem;
        }
        // emit against exact threshold bits
        for (int i = tid; i < nc; i += 256) {
            unsigned b = __float_as_uint(cval[i]);
            if (b > prefix) {
                int p = atomicAdd(&cnt_gt, 1);
                idxbuf[p] = cidx[i];
            } else if (b == prefix) {
                int p = atomicAdd(&cnt_eq, 1);
                if (p < 256) eqbuf[p] = cidx[i];
            }
        }
        __syncthreads();
    } else {
        // fallback: byte-radix passes from global (row is L2-hot)
        for (int shift = 16; shift >= 0; shift -= 8) {
            hist[tid] = 0;
            __syncthreads();
            const int ps = shift + 8;
            const unsigned pp = prefix >> ps;
            for (int i = tid; i < N_TOTAL; i += 256) {
                unsigned b = __float_as_uint(rowp[i]);
                if ((b >> ps) == pp) atomicAdd(&hist[(b >> shift) & 255], 1u);
            }
            __syncthreads();
            WARP_SELECT(krem)
            __syncthreads();
            prefix |= sh_sel << shift;
            krem = sh_krem;
        }
        for (int i = tid; i < N_TOTAL; i += 256) {
            unsigned b = __float_as_uint(rowp[i]);
            if (b > prefix) {
                int p = atomicAdd(&cnt_gt, 1);
                idxbuf[p] = i;
            } else if (b == prefix) {
                int p = atomicAdd(&cnt_eq, 1);
                if (p < 256) eqbuf[p] = i;
            }
        }
        __syncthreads();
    }
#undef WARP_SELECT

    // ---- choose krem lowest-index ties, softmax, scatter ----
    if (tid == 0) {
        int n = cnt_gt;
        int need = TOPK - n;
        if (cnt_eq <= 256) {
            for (int t = 0; t < need; ++t) {
                int best = 0x7fffffff, bj2 = 0;
                for (int j2 = 0; j2 < cnt_eq; ++j2) {
                    int vv = eqbuf[j2];
                    if (vv < best) { best = vv; bj2 = j2; }
                }
                idxbuf[n++] = best;
                eqbuf[bj2] = 0x7fffffff;
            }
        } else {
            for (int i = 0; i < N_TOTAL && need > 0; ++i)
                if (__float_as_uint(rowp[i]) == prefix) { idxbuf[n++] = i; --need; }
        }
    }
    __syncthreads();

    if (tid < TOPK) vbuf[tid] = rowp[idxbuf[tid]];
    __syncthreads();
    if (tid == 0) {
        float mx = -1e30f;
        for (int t = 0; t < TOPK; ++t) mx = fmaxf(mx, vbuf[t]);
        float ssum = 0.f;
        for (int t = 0; t < TOPK; ++t) {
            float e = expf(vbuf[t] - mx);
            ebuf[t] = e;
            ssum += e;
        }
        sh_inv = 1.f / ssum;
    }
    __syncthreads();
    if (tid < TOPK)
        S[(size_t)row * N_TOTAL + idxbuf[tid]] = ebuf[tid] * sh_inv;
}

// ===========================================================================
extern "C" void kernel_launch(void* const* d_in, const int* in_sizes, int n_in,
                              void* d_out, int out_size) {
    const float* inputs = (const float*)d_in[0];
    const float* W1     = (const float*)d_in[1];
    const float* b1     = (const float*)d_in[2];
    const float* gamma  = (const float*)d_in[3];
    const float* beta   = (const float*)d_in[4];
    const float* sw     = (const float*)d_in[5];
    const float* sb     = (const float*)d_in[6];

    float* outp = (float*)d_out;                       // [10000,128] outputs
    float* Sp   = outp + (size_t)N_TOTAL * D;          // [10000,10000] S

    gemm1_kernel<<<(N_TOTAL + 63) / 64, 256>>>(inputs, W1, b1);
    bn_kernel<<<N_TOTAL / BSZ, D>>>(gamma, beta, sw, outp);
    scores_kernel<<<TRI_BLOCKS, 256>>>(outp, sb);
    topk_kernel<<<N_TOTAL, 256>>>(Sp);
}

// round 5
// speedup vs baseline: 1.4019x; 1.0119x over previous
#include <cuda_runtime.h>

#define N_TOTAL 10000
#define D 128
#define BSZ 100
#define FEAT 3072
#define TOPK 50
#define NTILES 79          // ceil(10000/128)
#define TRI_BLOCKS (NTILES * (NTILES + 1) / 2)
#define CAP 2048           // candidate buffer capacity in topk
#define NF4 2500           // N_TOTAL/4

// ---------------- scratch (device globals: no allocation allowed) ----------
__device__ float g_x[(size_t)N_TOTAL * D];                 // pre-BN linear out
__device__ float g_y[(size_t)N_TOTAL * D];                 // -2 * out * sw
__device__ float g_a[N_TOTAL];                             // sum_k sw*out^2
__device__ float g_scores[(size_t)N_TOTAL * N_TOTAL];      // 400 MB scratch

// ---------------- f32x2 helpers (packed FFMA2) -----------------------------
__device__ __forceinline__ unsigned long long pack2(float x, float y) {
    unsigned long long r;
    asm("mov.b64 %0, {%1, %2};" : "=l"(r) : "f"(x), "f"(y));
    return r;
}
__device__ __forceinline__ float2 unpack2(unsigned long long v) {
    float x, y;
    asm("mov.b64 {%0, %1}, %2;" : "=f"(x), "=f"(y) : "l"(v));
    return make_float2(x, y);
}
__device__ __forceinline__ void fma2(unsigned long long& c,
                                     unsigned long long a,
                                     unsigned long long b) {
    asm("fma.rn.f32x2 %0, %1, %2, %3;" : "=l"(c) : "l"(a), "l"(b), "l"(c));
}

// ===========================================================================
// Kernel 1: x = inputs @ W1^T + b1      (M=10000, N=128, K=3072)
// ===========================================================================
__global__ void gemm1_kernel(const float* __restrict__ A,
                             const float* __restrict__ W,
                             const float* __restrict__ b1) {
    __shared__ __align__(16) float As[64][36];
    __shared__ float Bs[32][132];

    const int tid = threadIdx.x;
    const int mbase = blockIdx.x * 64;
    const int r0 = (tid >> 4) * 4;
    const int c0 = (tid & 15) * 8;

    unsigned long long acc[4][4];
#pragma unroll
    for (int i = 0; i < 4; ++i)
#pragma unroll
        for (int u = 0; u < 4; ++u) acc[i][u] = 0ULL;

    const int lr = tid >> 3;
    const int lk = (tid & 7) * 4;

    for (int kc = 0; kc < FEAT; kc += 32) {
#pragma unroll
        for (int it = 0; it < 2; ++it) {
            int m = mbase + it * 32 + lr;
            float4 v = make_float4(0.f, 0.f, 0.f, 0.f);
            if (m < N_TOTAL)
                v = *(const float4*)&A[(size_t)m * FEAT + kc + lk];
            *(float4*)&As[it * 32 + lr][lk] = v;
        }
#pragma unroll
        for (int it = 0; it < 4; ++it) {
            int n = it * 32 + lr;
            float4 v = *(const float4*)&W[(size_t)n * FEAT + kc + lk];
            Bs[lk + 0][n] = v.x;
            Bs[lk + 1][n] = v.y;
            Bs[lk + 2][n] = v.z;
            Bs[lk + 3][n] = v.w;
        }
        __syncthreads();

#pragma unroll 8
        for (int kk = 0; kk < 32; ++kk) {
            unsigned long long bv[4];
#pragma unroll
            for (int u = 0; u < 4; ++u)
                bv[u] = *(const unsigned long long*)&Bs[kk][c0 + 2 * u];
#pragma unroll
            for (int i = 0; i < 4; ++i) {
                float av = As[r0 + i][kk];
                unsigned long long ap = pack2(av, av);
#pragma unroll
                for (int u = 0; u < 4; ++u) fma2(acc[i][u], ap, bv[u]);
            }
        }
        __syncthreads();
    }

#pragma unroll
    for (int i = 0; i < 4; ++i) {
        int m = mbase + r0 + i;
        if (m < N_TOTAL) {
#pragma unroll
            for (int u = 0; u < 4; ++u) {
                float2 c = unpack2(acc[i][u]);
                c.x += b1[c0 + 2 * u];
                c.y += b1[c0 + 2 * u + 1];
                *(float2*)&g_x[(size_t)m * D + c0 + 2 * u] = c;
            }
        }
    }
}

// ===========================================================================
// Kernel 2: BatchNorm per micro-batch of 100 rows + fused y/a computation.
// ===========================================================================
__global__ void bn_kernel(const float* __restrict__ gamma,
                          const float* __restrict__ beta,
                          const float* __restrict__ sw,
                          float* __restrict__ outp) {
    const int b = blockIdx.x;
    const int c = threadIdx.x;
    __shared__ float arow[BSZ];
    if (c < BSZ) arow[c] = 0.f;

    const float* xb = g_x + (size_t)b * BSZ * D + c;
    float s = 0.f, s2 = 0.f;
    for (int r = 0; r < BSZ; ++r) {
        float v = xb[(size_t)r * D];
        s += v;
        s2 += v * v;
    }
    float mean = s * (1.f / BSZ);
    float var = s2 * (1.f / BSZ) - mean * mean;
    float rs = rsqrtf(var + 1e-5f);
    float g = gamma[c], be = beta[c], w = sw[c];
    __syncthreads();

    const int lane = c & 31;
    for (int r = 0; r < BSZ; ++r) {
        float v = xb[(size_t)r * D];
        float o = (v - mean) * rs * g + be;
        size_t idx = (size_t)(b * BSZ + r) * D + c;
        outp[idx] = o;
        g_y[idx] = -2.f * o * w;
        float contrib = w * o * o;
#pragma unroll
        for (int off = 16; off; off >>= 1)
            contrib += __shfl_down_sync(0xffffffffu, contrib, off);
        if (lane == 0) atomicAdd(&arow[r], contrib);
    }
    __syncthreads();
    if (c < BSZ) g_a[b * BSZ + c] = arow[c];
}

// ===========================================================================
// Kernel 3: scores[i,j] = relu(a_i + a_j + sb + y_i . out_j)   (SYMMETRIC)
// Triangular launch: only 3160 upper-tri tiles; mirror tile written too.
// ===========================================================================
__global__ void scores_kernel(const float* __restrict__ O,
                              const float* __restrict__ sbp) {
    int t = blockIdx.x;
    int bi = 0;
    while (t >= NTILES - bi) { t -= NTILES - bi; ++bi; }
    const int bj = bi + t;

    __shared__ __align__(16) float As[128][36];
    __shared__ float Bs[32][132];

    const int tid = threadIdx.x;
    const int ibase = bi * 128;
    const int jbase = bj * 128;
    const int r0 = (tid >> 4) * 8;
    const int c0 = (tid & 15) * 8;

    unsigned long long acc[8][4];
#pragma unroll
    for (int i = 0; i < 8; ++i)
#pragma unroll
        for (int u = 0; u < 4; ++u) acc[i][u] = 0ULL;

    const int lr = tid >> 3;
    const int lk = (tid & 7) * 4;

    for (int kc = 0; kc < D; kc += 32) {
#pragma unroll
        for (int it = 0; it < 4; ++it) {
            int m = ibase + it * 32 + lr;
            float4 v = make_float4(0.f, 0.f, 0.f, 0.f);
            if (m < N_TOTAL)
                v = *(const float4*)&g_y[(size_t)m * D + kc + lk];
            *(float4*)&As[it * 32 + lr][lk] = v;
        }
#pragma unroll
        for (int it = 0; it < 4; ++it) {
            int j = jbase + it * 32 + lr;
            float4 v = make_float4(0.f, 0.f, 0.f, 0.f);
            if (j < N_TOTAL)
                v = *(const float4*)&O[(size_t)j * D + kc + lk];
            Bs[lk + 0][it * 32 + lr] = v.x;
            Bs[lk + 1][it * 32 + lr] = v.y;
            Bs[lk + 2][it * 32 + lr] = v.z;
            Bs[lk + 3][it * 32 + lr] = v.w;
        }
        __syncthreads();

#pragma unroll 4
        for (int kk = 0; kk < 32; ++kk) {
            unsigned long long bv[4];
#pragma unroll
            for (int u = 0; u < 4; ++u)
                bv[u] = *(const unsigned long long*)&Bs[kk][c0 + 2 * u];
#pragma unroll
            for (int i = 0; i < 8; ++i) {
                float av = As[r0 + i][kk];
                unsigned long long ap = pack2(av, av);
#pragma unroll
                for (int u = 0; u < 4; ++u) fma2(acc[i][u], ap, bv[u]);
            }
        }
        __syncthreads();
    }

    const float sbv = *sbp;
    float ai[8], aj[8];
#pragma unroll
    for (int i = 0; i < 8; ++i) {
        int gi = ibase + r0 + i;
        ai[i] = (gi < N_TOTAL) ? g_a[gi] : 0.f;
    }
#pragma unroll
    for (int t2 = 0; t2 < 8; ++t2) {
        int gj = jbase + c0 + t2;
        aj[t2] = (gj < N_TOTAL) ? g_a[gj] : 0.f;
    }

    float sv[8][8];
#pragma unroll
    for (int i = 0; i < 8; ++i) {
        float base = ai[i] + sbv;
#pragma unroll
        for (int u = 0; u < 4; ++u) {
            float2 c = unpack2(acc[i][u]);
            sv[i][2 * u]     = fmaxf(base + aj[2 * u] + c.x, 0.f);
            sv[i][2 * u + 1] = fmaxf(base + aj[2 * u + 1] + c.y, 0.f);
        }
    }

    const bool full_i = (ibase + 128 <= N_TOTAL);
    const bool full_j = (jbase + 128 <= N_TOTAL);

    if (full_i && full_j) {
#pragma unroll
        for (int i = 0; i < 8; ++i) {
            size_t base = (size_t)(ibase + r0 + i) * N_TOTAL + jbase + c0;
            *(float4*)&g_scores[base]     = make_float4(sv[i][0], sv[i][1], sv[i][2], sv[i][3]);
            *(float4*)&g_scores[base + 4] = make_float4(sv[i][4], sv[i][5], sv[i][6], sv[i][7]);
        }
        if (bi != bj) {
#pragma unroll
            for (int j = 0; j < 8; ++j) {
                size_t base = (size_t)(jbase + c0 + j) * N_TOTAL + ibase + r0;
                *(float4*)&g_scores[base]     = make_float4(sv[0][j], sv[1][j], sv[2][j], sv[3][j]);
                *(float4*)&g_scores[base + 4] = make_float4(sv[4][j], sv[5][j], sv[6][j], sv[7][j]);
            }
        }
    } else {
#pragma unroll
        for (int i = 0; i < 8; ++i) {
            int gi = ibase + r0 + i;
            if (gi >= N_TOTAL) continue;
#pragma unroll
            for (int j = 0; j < 8; ++j) {
                int gj = jbase + c0 + j;
                if (gj >= N_TOTAL) continue;
                g_scores[(size_t)gi * N_TOTAL + gj] = sv[i][j];
                if (bi != bj)
                    g_scores[(size_t)gj * N_TOTAL + gi] = sv[i][j];
            }
        }
    }
}

// ===========================================================================
// Kernel 4: per-row exact top-50, v3 (fixed match_any divergence hang).
//   - pass 0: stream row (zero S), 4096-bin (12-bit) histogram with
//     warp-aggregated atomics; tail iteration uses plain atomics (safe
//     under divergence).
//   - two-level bin select, candidate-buffer finish, global fallback.
//   - tie-break: lowest index (matches lax.top_k); softmax; scatter.
// ===========================================================================
__global__ void __launch_bounds__(256) topk_kernel(float* __restrict__ S) {
    __shared__ unsigned hist4k[4096];
    __shared__ unsigned hist[256];
    __shared__ float cval[CAP];
    __shared__ int   cidx[CAP];
    __shared__ int idxbuf[64];
    __shared__ int eqbuf[256];
    __shared__ float vbuf[TOPK];
    __shared__ float ebuf[TOPK];
    __shared__ int cnt_gt, cnt_eq, cnt_c;
    __shared__ unsigned sh_sel;
    __shared__ int sh_krem, sh_binc;
    __shared__ unsigned sh_pfx12;
    __shared__ float sh_inv;

    const int row = blockIdx.x;
    const int tid = threadIdx.x;
    const int lane = tid & 31;

    const float* rowp = g_scores + (size_t)row * N_TOTAL;
    const float4* rp4 = (const float4*)rowp;
    float4* sp4 = (float4*)(S + (size_t)row * N_TOTAL);

    for (int i = tid; i < 4096; i += 256) hist4k[i] = 0;
    if (tid == 0) { cnt_gt = 0; cnt_eq = 0; cnt_c = 0; }
    __syncthreads();

    // ---- pass 0: zero S + 12-bit histogram ----
    // Iterations 0..8 are full (9*256=2304 <= 2500): every lane active, so
    // full-mask __match_any_sync is legal. Tail uses plain atomics.
    const float4 z = make_float4(0.f, 0.f, 0.f, 0.f);
#pragma unroll
    for (int it = 0; it < 9; ++it) {
        int i4 = it * 256 + tid;            // always < 2304 <= NF4
        float4 val = rp4[i4];
        sp4[i4] = z;
        unsigned bb[4] = { __float_as_uint(val.x) >> 20,
                           __float_as_uint(val.y) >> 20,
                           __float_as_uint(val.z) >> 20,
                           __float_as_uint(val.w) >> 20 };
#pragma unroll
        for (int q = 0; q < 4; ++q) {
            unsigned m = __match_any_sync(0xffffffffu, bb[q]);
            if ((int)(__ffs(m) - 1) == lane)
                atomicAdd(&hist4k[bb[q]], (unsigned)__popc(m));
        }
    }
    {   // tail: i4 in [2304, 2500) -> tid < 196 only; plain atomics
        int i4 = 9 * 256 + tid;
        if (i4 < NF4) {
            float4 val = rp4[i4];
            sp4[i4] = z;
            atomicAdd(&hist4k[__float_as_uint(val.x) >> 20], 1u);
            atomicAdd(&hist4k[__float_as_uint(val.y) >> 20], 1u);
            atomicAdd(&hist4k[__float_as_uint(val.z) >> 20], 1u);
            atomicAdd(&hist4k[__float_as_uint(val.w) >> 20], 1u);
        }
    }
    __syncthreads();

    // ---- warp-0 bin selection on a 256-entry array -----------------------
#define WARP_SELECT(ARR, KREM)                                                \
    if (tid < 32) {                                                           \
        unsigned h[8], ls[8];                                                 \
        int b0 = lane * 8;                                                    \
        _Pragma("unroll")                                                     \
        for (int j = 0; j < 8; ++j) h[j] = (ARR)[b0 + j];                     \
        ls[7] = h[7];                                                         \
        _Pragma("unroll")                                                     \
        for (int j = 6; j >= 0; --j) ls[j] = ls[j + 1] + h[j];                \
        unsigned tot = ls[0];                                                 \
        unsigned ss = tot;                                                    \
        _Pragma("unroll")                                                     \
        for (int off = 1; off < 32; off <<= 1) {                              \
            unsigned o = __shfl_down_sync(0xffffffffu, ss, off);              \
            if (lane + off < 32) ss += o;                                     \
        }                                                                     \
        unsigned above = ss - tot;                                            \
        int best = -1;                                                        \
        _Pragma("unroll")                                                     \
        for (int j = 7; j >= 0; --j)                                          \
            if (best < 0 && above + ls[j] >= (unsigned)(KREM)) best = j;      \
        unsigned m = __ballot_sync(0xffffffffu, best >= 0);                   \
        int hi = 31 - __clz((int)m);                                          \
        if (lane == hi) {                                                     \
            unsigned Sb = above + ls[best];                                   \
            sh_sel = (unsigned)(b0 + best);                                   \
            sh_binc = (int)h[best];                                           \
            sh_krem = (KREM) - (int)(Sb - h[best]);                           \
        }                                                                     \
    }

    // super-bin sums (each thread sums 16 of the 4096)
    {
        unsigned s16 = 0;
#pragma unroll
        for (int j = 0; j < 16; ++j) s16 += hist4k[tid * 16 + j];
        hist[tid] = s16;
    }
    __syncthreads();
    WARP_SELECT(hist, TOPK)
    __syncthreads();

    // inner select within super-bin (16 bins, serial — cheap)
    if (tid == 0) {
        unsigned sb = sh_sel;
        int krem2 = sh_krem;
        unsigned cum = 0;
        for (int j = 15; j >= 0; --j) {
            unsigned h = hist4k[sb * 16 + j];
            if (cum + h >= (unsigned)krem2) {
                sh_pfx12 = sb * 16 + (unsigned)j;
                sh_krem = krem2 - (int)cum;
                sh_binc = (int)h;
                break;
            }
            cum += h;
        }
    }
    __syncthreads();

    const unsigned pfx12 = sh_pfx12;
    unsigned prefix = pfx12 << 20;
    int krem = sh_krem;
    const int binc = sh_binc;

    // pass descriptors: {prefix-check shift, bin shift, mask}
    const int PS[3] = {20, 12, 4};
    const int BS_[3] = {12, 4, 0};
    const unsigned MK[3] = {255u, 255u, 15u};

    if (binc <= CAP) {
        // ---- collect pass (row re-read, L2-hot) ----
#pragma unroll
        for (int it = 0; it < 10; ++it) {
            int i4 = it * 256 + tid;
            if (i4 < NF4) {
                float4 val = rp4[i4];
                unsigned b4[4] = { __float_as_uint(val.x), __float_as_uint(val.y),
                                   __float_as_uint(val.z), __float_as_uint(val.w) };
#pragma unroll
                for (int q = 0; q < 4; ++q) {
                    unsigned hp = b4[q] >> 20;
                    if (hp > pfx12) {
                        int p = atomicAdd(&cnt_gt, 1);
                        idxbuf[p] = 4 * i4 + q;
                    } else if (hp == pfx12) {
                        int p = atomicAdd(&cnt_c, 1);
                        cval[p] = __uint_as_float(b4[q]);
                        cidx[p] = 4 * i4 + q;
                    }
                }
            }
        }
        __syncthreads();
        const int nc = cnt_c;

        // ---- 3 small radix passes over shared candidates ----
#pragma unroll
        for (int ps = 0; ps < 3; ++ps) {
            hist[tid] = 0;
            __syncthreads();
            const unsigned pp = prefix >> PS[ps];
            for (int i = tid; i < nc; i += 256) {
                unsigned b = __float_as_uint(cval[i]);
                if ((b >> PS[ps]) == pp)
                    atomicAdd(&hist[(b >> BS_[ps]) & MK[ps]], 1u);
            }
            __syncthreads();
            WARP_SELECT(hist, krem)
            __syncthreads();
            prefix |= sh_sel << BS_[ps];
            krem = sh_krem;
        }
        // emit against exact threshold bits
        for (int i = tid; i < nc; i += 256) {
            unsigned b = __float_as_uint(cval[i]);
            if (b > prefix) {
                int p = atomicAdd(&cnt_gt, 1);
                idxbuf[p] = cidx[i];
            } else if (b == prefix) {
                int p = atomicAdd(&cnt_eq, 1);
                if (p < 256) eqbuf[p] = cidx[i];
            }
        }
        __syncthreads();
    } else {
        // ---- fallback: finish radix from global (row L2-hot) ----
#pragma unroll
        for (int ps = 0; ps < 3; ++ps) {
            hist[tid] = 0;
            __syncthreads();
            const unsigned pp = prefix >> PS[ps];
            for (int i = tid; i < N_TOTAL; i += 256) {
                unsigned b = __float_as_uint(rowp[i]);
                if ((b >> PS[ps]) == pp)
                    atomicAdd(&hist[(b >> BS_[ps]) & MK[ps]], 1u);
            }
            __syncthreads();
            WARP_SELECT(hist, krem)
            __syncthreads();
            prefix |= sh_sel << BS_[ps];
            krem = sh_krem;
        }
        for (int i = tid; i < N_TOTAL; i += 256) {
            unsigned b = __float_as_uint(rowp[i]);
            if (b > prefix) {
                int p = atomicAdd(&cnt_gt, 1);
                idxbuf[p] = i;
            } else if (b == prefix) {
                int p = atomicAdd(&cnt_eq, 1);
                if (p < 256) eqbuf[p] = i;
            }
        }
        __syncthreads();
    }
#undef WARP_SELECT

    // ---- choose krem lowest-index ties, softmax, scatter ----
    if (tid == 0) {
        int n = cnt_gt;
        int need = TOPK - n;
        if (cnt_eq <= 256) {
            for (int t = 0; t < need; ++t) {
                int best = 0x7fffffff, bj2 = 0;
                for (int j2 = 0; j2 < cnt_eq; ++j2) {
                    int vv = eqbuf[j2];
                    if (vv < best) { best = vv; bj2 = j2; }
                }
                idxbuf[n++] = best;
                eqbuf[bj2] = 0x7fffffff;
            }
        } else {
            for (int i = 0; i < N_TOTAL && need > 0; ++i)
                if (__float_as_uint(rowp[i]) == prefix) { idxbuf[n++] = i; --need; }
        }
    }
    __syncthreads();

    if (tid < TOPK) vbuf[tid] = rowp[idxbuf[tid]];
    __syncthreads();
    if (tid == 0) {
        float mx = -1e30f;
        for (int t = 0; t < TOPK; ++t) mx = fmaxf(mx, vbuf[t]);
        float ssum = 0.f;
        for (int t = 0; t < TOPK; ++t) {
            float e = expf(vbuf[t] - mx);
            ebuf[t] = e;
            ssum += e;
        }
        sh_inv = 1.f / ssum;
    }
    __syncthreads();
    if (tid < TOPK)
        S[(size_t)row * N_TOTAL + idxbuf[tid]] = ebuf[tid] * sh_inv;
}

// ===========================================================================
extern "C" void kernel_launch(void* const* d_in, const int* in_sizes, int n_in,
                              void* d_out, int out_size) {
    const float* inputs = (const float*)d_in[0];
    const float* W1     = (const float*)d_in[1];
    const float* b1     = (const float*)d_in[2];
    const float* gamma  = (const float*)d_in[3];
    const float* beta   = (const float*)d_in[4];
    const float* sw     = (const float*)d_in[5];
    const float* sb     = (const float*)d_in[6];

    float* outp = (float*)d_out;                       // [10000,128] outputs
    float* Sp   = outp + (size_t)N_TOTAL * D;          // [10000,10000] S

    gemm1_kernel<<<(N_TOTAL + 63) / 64, 256>>>(inputs, W1, b1);
    bn_kernel<<<N_TOTAL / BSZ, D>>>(gamma, beta, sw, outp);
    scores_kernel<<<TRI_BLOCKS, 256>>>(outp, sb);
    topk_kernel<<<N_TOTAL, 256>>>(Sp);
}

// round 6
// speedup vs baseline: 1.5138x; 1.0798x over previous
#include <cuda_runtime.h>

#define N_TOTAL 10000
#define D 128
#define BSZ 100
#define FEAT 3072
#define TOPK 50
#define NTILES 79          // ceil(10000/128)
#define TRI_BLOCKS (NTILES * (NTILES + 1) / 2)
#define CAP 2048           // candidate buffer capacity in topk
#define NF4 2500           // N_TOTAL/4

// ---------------- scratch (device globals: no allocation allowed) ----------
__device__ float g_x[(size_t)N_TOTAL * D];                 // pre-BN linear out
__device__ float g_y[(size_t)N_TOTAL * D];                 // -2 * out * sw
__device__ float g_a[N_TOTAL];                             // sum_k sw*out^2
__device__ float g_scores[(size_t)N_TOTAL * N_TOTAL];      // 400 MB scratch

// ---------------- f32x2 helpers (packed FFMA2) -----------------------------
__device__ __forceinline__ unsigned long long pack2(float x, float y) {
    unsigned long long r;
    asm("mov.b64 %0, {%1, %2};" : "=l"(r) : "f"(x), "f"(y));
    return r;
}
__device__ __forceinline__ float2 unpack2(unsigned long long v) {
    float x, y;
    asm("mov.b64 {%0, %1}, %2;" : "=f"(x), "=f"(y) : "l"(v));
    return make_float2(x, y);
}
__device__ __forceinline__ void fma2(unsigned long long& c,
                                     unsigned long long a,
                                     unsigned long long b) {
    asm("fma.rn.f32x2 %0, %1, %2, %3;" : "=l"(c) : "l"(a), "l"(b), "l"(c));
}

// ===========================================================================
// Kernel 1: x = inputs @ W1^T + b1      (M=10000, N=128, K=3072)
// ===========================================================================
__global__ void gemm1_kernel(const float* __restrict__ A,
                             const float* __restrict__ W,
                             const float* __restrict__ b1) {
    __shared__ __align__(16) float As[64][36];
    __shared__ float Bs[32][132];

    const int tid = threadIdx.x;
    const int mbase = blockIdx.x * 64;
    const int r0 = (tid >> 4) * 4;
    const int c0 = (tid & 15) * 8;

    unsigned long long acc[4][4];
#pragma unroll
    for (int i = 0; i < 4; ++i)
#pragma unroll
        for (int u = 0; u < 4; ++u) acc[i][u] = 0ULL;

    const int lr = tid >> 3;
    const int lk = (tid & 7) * 4;

    for (int kc = 0; kc < FEAT; kc += 32) {
#pragma unroll
        for (int it = 0; it < 2; ++it) {
            int m = mbase + it * 32 + lr;
            float4 v = make_float4(0.f, 0.f, 0.f, 0.f);
            if (m < N_TOTAL)
                v = *(const float4*)&A[(size_t)m * FEAT + kc + lk];
            *(float4*)&As[it * 32 + lr][lk] = v;
        }
#pragma unroll
        for (int it = 0; it < 4; ++it) {
            int n = it * 32 + lr;
            float4 v = *(const float4*)&W[(size_t)n * FEAT + kc + lk];
            Bs[lk + 0][n] = v.x;
            Bs[lk + 1][n] = v.y;
            Bs[lk + 2][n] = v.z;
            Bs[lk + 3][n] = v.w;
        }
        __syncthreads();

#pragma unroll 8
        for (int kk = 0; kk < 32; ++kk) {
            unsigned long long bv[4];
#pragma unroll
            for (int u = 0; u < 4; ++u)
                bv[u] = *(const unsigned long long*)&Bs[kk][c0 + 2 * u];
#pragma unroll
            for (int i = 0; i < 4; ++i) {
                float av = As[r0 + i][kk];
                unsigned long long ap = pack2(av, av);
#pragma unroll
                for (int u = 0; u < 4; ++u) fma2(acc[i][u], ap, bv[u]);
            }
        }
        __syncthreads();
    }

#pragma unroll
    for (int i = 0; i < 4; ++i) {
        int m = mbase + r0 + i;
        if (m < N_TOTAL) {
#pragma unroll
            for (int u = 0; u < 4; ++u) {
                float2 c = unpack2(acc[i][u]);
                c.x += b1[c0 + 2 * u];
                c.y += b1[c0 + 2 * u + 1];
                *(float2*)&g_x[(size_t)m * D + c0 + 2 * u] = c;
            }
        }
    }
}

// ===========================================================================
// Kernel 2: BatchNorm per micro-batch of 100 rows + fused y/a computation.
// ===========================================================================
__global__ void bn_kernel(const float* __restrict__ gamma,
                          const float* __restrict__ beta,
                          const float* __restrict__ sw,
                          float* __restrict__ outp) {
    const int b = blockIdx.x;
    const int c = threadIdx.x;
    __shared__ float arow[BSZ];
    if (c < BSZ) arow[c] = 0.f;

    const float* xb = g_x + (size_t)b * BSZ * D + c;
    float s = 0.f, s2 = 0.f;
    for (int r = 0; r < BSZ; ++r) {
        float v = xb[(size_t)r * D];
        s += v;
        s2 += v * v;
    }
    float mean = s * (1.f / BSZ);
    float var = s2 * (1.f / BSZ) - mean * mean;
    float rs = rsqrtf(var + 1e-5f);
    float g = gamma[c], be = beta[c], w = sw[c];
    __syncthreads();

    const int lane = c & 31;
    for (int r = 0; r < BSZ; ++r) {
        float v = xb[(size_t)r * D];
        float o = (v - mean) * rs * g + be;
        size_t idx = (size_t)(b * BSZ + r) * D + c;
        outp[idx] = o;
        g_y[idx] = -2.f * o * w;
        float contrib = w * o * o;
#pragma unroll
        for (int off = 16; off; off >>= 1)
            contrib += __shfl_down_sync(0xffffffffu, contrib, off);
        if (lane == 0) atomicAdd(&arow[r], contrib);
    }
    __syncthreads();
    if (c < BSZ) g_a[b * BSZ + c] = arow[c];
}

// ===========================================================================
// Kernel 3: scores[i,j] = relu(a_i + a_j + sb + y_i . out_j)   (SYMMETRIC)
// Triangular launch: only 3160 upper-tri tiles; mirror tile written too.
// ===========================================================================
__global__ void scores_kernel(const float* __restrict__ O,
                              const float* __restrict__ sbp) {
    int t = blockIdx.x;
    int bi = 0;
    while (t >= NTILES - bi) { t -= NTILES - bi; ++bi; }
    const int bj = bi + t;

    __shared__ __align__(16) float As[128][36];
    __shared__ float Bs[32][132];

    const int tid = threadIdx.x;
    const int ibase = bi * 128;
    const int jbase = bj * 128;
    const int r0 = (tid >> 4) * 8;
    const int c0 = (tid & 15) * 8;

    unsigned long long acc[8][4];
#pragma unroll
    for (int i = 0; i < 8; ++i)
#pragma unroll
        for (int u = 0; u < 4; ++u) acc[i][u] = 0ULL;

    const int lr = tid >> 3;
    const int lk = (tid & 7) * 4;

    for (int kc = 0; kc < D; kc += 32) {
#pragma unroll
        for (int it = 0; it < 4; ++it) {
            int m = ibase + it * 32 + lr;
            float4 v = make_float4(0.f, 0.f, 0.f, 0.f);
            if (m < N_TOTAL)
                v = *(const float4*)&g_y[(size_t)m * D + kc + lk];
            *(float4*)&As[it * 32 + lr][lk] = v;
        }
#pragma unroll
        for (int it = 0; it < 4; ++it) {
            int j = jbase + it * 32 + lr;
            float4 v = make_float4(0.f, 0.f, 0.f, 0.f);
            if (j < N_TOTAL)
                v = *(const float4*)&O[(size_t)j * D + kc + lk];
            Bs[lk + 0][it * 32 + lr] = v.x;
            Bs[lk + 1][it * 32 + lr] = v.y;
            Bs[lk + 2][it * 32 + lr] = v.z;
            Bs[lk + 3][it * 32 + lr] = v.w;
        }
        __syncthreads();

#pragma unroll 4
        for (int kk = 0; kk < 32; ++kk) {
            unsigned long long bv[4];
#pragma unroll
            for (int u = 0; u < 4; ++u)
                bv[u] = *(const unsigned long long*)&Bs[kk][c0 + 2 * u];
#pragma unroll
            for (int i = 0; i < 8; ++i) {
                float av = As[r0 + i][kk];
                unsigned long long ap = pack2(av, av);
#pragma unroll
                for (int u = 0; u < 4; ++u) fma2(acc[i][u], ap, bv[u]);
            }
        }
        __syncthreads();
    }

    const float sbv = *sbp;
    float ai[8], aj[8];
#pragma unroll
    for (int i = 0; i < 8; ++i) {
        int gi = ibase + r0 + i;
        ai[i] = (gi < N_TOTAL) ? g_a[gi] : 0.f;
    }
#pragma unroll
    for (int t2 = 0; t2 < 8; ++t2) {
        int gj = jbase + c0 + t2;
        aj[t2] = (gj < N_TOTAL) ? g_a[gj] : 0.f;
    }

    float sv[8][8];
#pragma unroll
    for (int i = 0; i < 8; ++i) {
        float base = ai[i] + sbv;
#pragma unroll
        for (int u = 0; u < 4; ++u) {
            float2 c = unpack2(acc[i][u]);
            sv[i][2 * u]     = fmaxf(base + aj[2 * u] + c.x, 0.f);
            sv[i][2 * u + 1] = fmaxf(base + aj[2 * u + 1] + c.y, 0.f);
        }
    }

    const bool full_i = (ibase + 128 <= N_TOTAL);
    const bool full_j = (jbase + 128 <= N_TOTAL);

    if (full_i && full_j) {
#pragma unroll
        for (int i = 0; i < 8; ++i) {
            size_t base = (size_t)(ibase + r0 + i) * N_TOTAL + jbase + c0;
            *(float4*)&g_scores[base]     = make_float4(sv[i][0], sv[i][1], sv[i][2], sv[i][3]);
            *(float4*)&g_scores[base + 4] = make_float4(sv[i][4], sv[i][5], sv[i][6], sv[i][7]);
        }
        if (bi != bj) {
#pragma unroll
            for (int j = 0; j < 8; ++j) {
                size_t base = (size_t)(jbase + c0 + j) * N_TOTAL + ibase + r0;
                *(float4*)&g_scores[base]     = make_float4(sv[0][j], sv[1][j], sv[2][j], sv[3][j]);
                *(float4*)&g_scores[base + 4] = make_float4(sv[4][j], sv[5][j], sv[6][j], sv[7][j]);
            }
        }
    } else {
#pragma unroll
        for (int i = 0; i < 8; ++i) {
            int gi = ibase + r0 + i;
            if (gi >= N_TOTAL) continue;
#pragma unroll
            for (int j = 0; j < 8; ++j) {
                int gj = jbase + c0 + j;
                if (gj >= N_TOTAL) continue;
                g_scores[(size_t)gi * N_TOTAL + gj] = sv[i][j];
                if (bi != bj)
                    g_scores[(size_t)gj * N_TOTAL + gi] = sv[i][j];
            }
        }
    }
}

// ===========================================================================
// Kernel 4: per-row exact top-50, v4 — single-pass threshold buffer.
//   Stream the row once (fused S zeroing); push values >= thr into a shared
//   candidate buffer (warp-aggregated counter). On near-overflow (uniform
//   chunk boundary), exact-select the 50th-so-far and compact (>= keeps
//   bit-exact ties). Final: exact 4x8-bit radix select over buffer, ties ->
//   lowest index (lax.top_k), softmax, scatter.
// ===========================================================================
__global__ void __launch_bounds__(256) topk_kernel(float* __restrict__ S) {
    __shared__ float bval[CAP];
    __shared__ int   bidx[CAP];
    __shared__ unsigned hist[256];
    __shared__ int idxbuf[64];
    __shared__ int eqbuf[256];
    __shared__ float vbuf[TOPK];
    __shared__ float ebuf[TOPK];
    __shared__ int bcount, cnt_gt, cnt_eq;
    __shared__ unsigned sh_sel;
    __shared__ int sh_krem, sh_binc;
    __shared__ unsigned sh_thr;
    __shared__ float sh_inv;

    const int row = blockIdx.x;
    const int tid = threadIdx.x;
    const int lane = tid & 31;

    const float* rowp = g_scores + (size_t)row * N_TOTAL;
    const float4* rp4 = (const float4*)rowp;
    float4* sp4 = (float4*)(S + (size_t)row * N_TOTAL);

    if (tid == 0) { bcount = 0; cnt_gt = 0; cnt_eq = 0; sh_thr = 0; }
    __syncthreads();

    // ---- warp-0 suffix-scan bin selection over hist[256] ----
#define WARP_SELECT(ARR, KREM)                                                \
    if (tid < 32) {                                                           \
        unsigned h[8], ls[8];                                                 \
        int b0 = lane * 8;                                                    \
        _Pragma("unroll")                                                     \
        for (int j = 0; j < 8; ++j) h[j] = (ARR)[b0 + j];                     \
        ls[7] = h[7];                                                         \
        _Pragma("unroll")                                                     \
        for (int j = 6; j >= 0; --j) ls[j] = ls[j + 1] + h[j];                \
        unsigned tot = ls[0];                                                 \
        unsigned ss = tot;                                                    \
        _Pragma("unroll")                                                     \
        for (int off = 1; off < 32; off <<= 1) {                              \
            unsigned o = __shfl_down_sync(0xffffffffu, ss, off);              \
            if (lane + off < 32) ss += o;                                     \
        }                                                                     \
        unsigned above = ss - tot;                                            \
        int best = -1;                                                        \
        _Pragma("unroll")                                                     \
        for (int j = 7; j >= 0; --j)                                          \
            if (best < 0 && above + ls[j] >= (unsigned)(KREM)) best = j;      \
        unsigned m = __ballot_sync(0xffffffffu, best >= 0);                   \
        int hi = 31 - __clz((int)m);                                          \
        if (lane == hi) {                                                     \
            unsigned Sb = above + ls[best];                                   \
            sh_sel = (unsigned)(b0 + best);                                   \
            sh_binc = (int)h[best];                                           \
            sh_krem = (KREM) - (int)(Sb - h[best]);                           \
        }                                                                     \
    }

    // ---- exact K-th largest over shared buffer bval[0..CNT) -------------
    // On exit: PREFIX = float bits of the K-th largest; KREM = #ties needed.
#define EXACT_SELECT(CNT, KINIT, PREFIX, KREM)                                \
    {                                                                         \
        (PREFIX) = 0; (KREM) = (KINIT);                                       \
        const int SHS[4] = {24, 16, 8, 0};                                    \
        const unsigned HMS[4] = {0u, 0xFF000000u, 0xFFFF0000u, 0xFFFFFF00u};  \
        for (int ps = 0; ps < 4; ++ps) {                                      \
            hist[tid] = 0;                                                    \
            __syncthreads();                                                  \
            for (int i = tid; i < (CNT); i += 256) {                          \
                unsigned b = __float_as_uint(bval[i]);                        \
                if ((b & HMS[ps]) == ((PREFIX) & HMS[ps]))                    \
                    atomicAdd(&hist[(b >> SHS[ps]) & 255u], 1u);              \
            }                                                                 \
            __syncthreads();                                                  \
            WARP_SELECT(hist, (KREM))                                         \
            __syncthreads();                                                  \
            (PREFIX) |= sh_sel << SHS[ps];                                    \
            (KREM) = sh_krem;                                                 \
            __syncthreads();                                                  \
        }                                                                     \
    }

    // ---- warp-aggregated buffer push -------------------------------------
#define PUSH(V, IDX)                                                          \
    {                                                                         \
        unsigned b_ = __float_as_uint(V);                                     \
        if (b_ >= thr) {                                                      \
            unsigned mk = __activemask();                                     \
            int ldr = __ffs(mk) - 1;                                          \
            int rk = __popc(mk & ((1u << lane) - 1));                         \
            int bs;                                                           \
            if (lane == ldr) bs = atomicAdd(&bcount, __popc(mk));             \
            bs = __shfl_sync(mk, bs, ldr);                                    \
            int p_ = bs + rk;                                                 \
            if (p_ < CAP) { bval[p_] = (V); bidx[p_] = (IDX); }               \
        }                                                                     \
    }

    unsigned thr = 0;
    const float4 z = make_float4(0.f, 0.f, 0.f, 0.f);

    for (int chunk = 0; chunk < 10; ++chunk) {
        // uniform compaction check (bcount stable: after __syncthreads)
        if (bcount > CAP - 1024) {
            unsigned pfx; int kr;
            EXACT_SELECT(bcount, TOPK, pfx, kr)
            (void)kr;
            const int cnt = bcount;
            float mv[8]; int mi[8]; int mc = 0;
            for (int i = tid; i < cnt; i += 256) {
                unsigned b = __float_as_uint(bval[i]);
                if (b >= pfx) { mv[mc] = bval[i]; mi[mc] = bidx[i]; ++mc; }
            }
            __syncthreads();
            if (tid == 0) { bcount = 0; sh_thr = pfx; }
            __syncthreads();
            for (int j = 0; j < mc; ++j) {
                int p = atomicAdd(&bcount, 1);
                bval[p] = mv[j]; bidx[p] = mi[j];
            }
            __syncthreads();
            thr = sh_thr;
        }

        // stream one chunk: 256 float4 = 1024 elements
        int i4 = chunk * 256 + tid;
        if (i4 < NF4) {
            float4 val = rp4[i4];
            sp4[i4] = z;
            PUSH(val.x, 4 * i4 + 0)
            PUSH(val.y, 4 * i4 + 1)
            PUSH(val.z, 4 * i4 + 2)
            PUSH(val.w, 4 * i4 + 3)
        }
        __syncthreads();
    }

    // ---- final exact select over the candidate buffer ----
    const int nc = bcount;
    unsigned prefix; int krem;
    EXACT_SELECT(nc, TOPK, prefix, krem)

    for (int i = tid; i < nc; i += 256) {
        unsigned b = __float_as_uint(bval[i]);
        if (b > prefix) {
            int p = atomicAdd(&cnt_gt, 1);
            idxbuf[p] = bidx[i];                 // <= 49 guaranteed
        } else if (b == prefix) {
            int p = atomicAdd(&cnt_eq, 1);
            if (p < 256) eqbuf[p] = bidx[i];
        }
    }
    __syncthreads();

    // ---- choose krem lowest-index ties ----
    if (tid == 0) {
        int n = cnt_gt;
        int need = TOPK - n;
        if (cnt_eq <= 256) {
            for (int t = 0; t < need; ++t) {
                int best = 0x7fffffff, bj2 = 0;
                for (int j2 = 0; j2 < cnt_eq; ++j2) {
                    int vv = eqbuf[j2];
                    if (vv < best) { best = vv; bj2 = j2; }
                }
                idxbuf[n++] = best;
                eqbuf[bj2] = 0x7fffffff;
            }
        } else {
            // ultra-rare massive-tie path: all ties live in the buffer
            for (int t = 0; t < need; ++t) {
                int best = 0x7fffffff, bj2 = -1;
                for (int i = 0; i < nc; ++i) {
                    if (__float_as_uint(bval[i]) == prefix && bidx[i] < best) {
                        best = bidx[i]; bj2 = i;
                    }
                }
                idxbuf[n++] = best;
                if (bj2 >= 0) bidx[bj2] = 0x7fffffff;
            }
        }
    }
    __syncthreads();

    if (tid < TOPK) vbuf[tid] = rowp[idxbuf[tid]];
    __syncthreads();
    if (tid == 0) {
        float mx = -1e30f;
        for (int t = 0; t < TOPK; ++t) mx = fmaxf(mx, vbuf[t]);
        float ssum = 0.f;
        for (int t = 0; t < TOPK; ++t) {
            float e = expf(vbuf[t] - mx);
            ebuf[t] = e;
            ssum += e;
        }
        sh_inv = 1.f / ssum;
    }
    __syncthreads();
    if (tid < TOPK)
        S[(size_t)row * N_TOTAL + idxbuf[tid]] = ebuf[tid] * sh_inv;

#undef PUSH
#undef EXACT_SELECT
#undef WARP_SELECT
}

// ===========================================================================
extern "C" void kernel_launch(void* const* d_in, const int* in_sizes, int n_in,
                              void* d_out, int out_size) {
    const float* inputs = (const float*)d_in[0];
    const float* W1     = (const float*)d_in[1];
    const float* b1     = (const float*)d_in[2];
    const float* gamma  = (const float*)d_in[3];
    const float* beta   = (const float*)d_in[4];
    const float* sw     = (const float*)d_in[5];
    const float* sb     = (const float*)d_in[6];

    float* outp = (float*)d_out;                       // [10000,128] outputs
    float* Sp   = outp + (size_t)N_TOTAL * D;          // [10000,10000] S

    gemm1_kernel<<<(N_TOTAL + 63) / 64, 256>>>(inputs, W1, b1);
    bn_kernel<<<N_TOTAL / BSZ, D>>>(gamma, beta, sw, outp);
    scores_kernel<<<TRI_BLOCKS, 256>>>(outp, sb);
    topk_kernel<<<N_TOTAL, 256>>>(Sp);
}